// round 1
// baseline (speedup 1.0000x reference)
#include <cuda_runtime.h>

// Problem constants
#define BB   8
#define NN   8192
#define SS   2048
#define C1K  128
#define C2K  256
#define INCH 384            // C1 + C2
#define H1   256
#define H2   128
#define MM   (BB * NN)      // 65536 total points

// ---------------- scratch (static device globals; no allocation) ----------------
__device__ float g_X  [MM * (size_t)INCH];   // concat(p1, interp)  [M, 384]
__device__ float g_Y1 [MM * (size_t)H1];     // pre-BN layer1 out   [M, 256]
__device__ float g_Y2 [MM * (size_t)H2];     // pre-BN layer2 out   [M, 128]
__device__ float g_P2T[BB * (size_t)SS * C2K]; // points2 transposed [B, S, C2]
__device__ int   g_idx[MM * 3];
__device__ float g_wt [MM * 3];
__device__ float g_sum1[H1], g_sq1[H1], g_sum2[H2], g_sq2[H2];
__device__ float g_sc1 [H1], g_sh1[H1], g_sc2 [H2], g_sh2[H2];

// ---------------- zero the per-channel accumulators ----------------
__global__ void zero_stats_kernel() {
    int t = threadIdx.x;
    g_sum1[t] = 0.f; g_sq1[t] = 0.f;
    if (t < H2) { g_sum2[t] = 0.f; g_sq2[t] = 0.f; }
}

// ---------------- tiled transpose: src [B][C][L] -> dst [B][L][ldDst] ----------------
__global__ void transpose_kernel(const float* __restrict__ src, float* __restrict__ dst,
                                 int C, int L, int ldDst)
{
    __shared__ float tile[32][33];
    int b  = blockIdx.z;
    int l0 = blockIdx.x * 32, c0 = blockIdx.y * 32;
    const float* s = src + (size_t)b * C * L;
    float*       d = dst + (size_t)b * L * ldDst;
    int tx = threadIdx.x, ty = threadIdx.y;
#pragma unroll
    for (int i = 0; i < 4; i++)
        tile[ty + i * 8][tx] = s[(size_t)(c0 + ty + i * 8) * L + l0 + tx];
    __syncthreads();
#pragma unroll
    for (int i = 0; i < 4; i++)
        d[(size_t)(l0 + ty + i * 8) * ldDst + c0 + tx] = tile[tx][ty + i * 8];
}

// ---------------- 3-NN over S=2048 candidates (smem resident) ----------------
__global__ void knn_kernel(const float* __restrict__ xyz1, const float* __restrict__ xyz2)
{
    __shared__ float4 sq[SS];               // {x, y, z, |q|^2}  32KB
    int b = blockIdx.y;
    const float* x2 = xyz2 + (size_t)b * 3 * SS;
    for (int s = threadIdx.x; s < SS; s += blockDim.x) {
        float qx = x2[s], qy = x2[SS + s], qz = x2[2 * SS + s];
        sq[s] = make_float4(qx, qy, qz, qx * qx + qy * qy + qz * qz);
    }
    __syncthreads();

    int n = blockIdx.x * blockDim.x + threadIdx.x;
    const float* x1 = xyz1 + (size_t)b * 3 * NN;
    float px = x1[n], py = x1[NN + n], pz = x1[2 * NN + n];
    float mx = -2.f * px, my = -2.f * py, mz = -2.f * pz;
    float p2 = px * px + py * py + pz * pz;

    float d0 = 1e30f, d1 = 1e30f, d2 = 1e30f;
    int   i0 = 0, i1 = 0, i2 = 0;
#pragma unroll 4
    for (int s = 0; s < SS; s++) {
        float4 q = sq[s];
        float t = fmaf(mx, q.x, fmaf(my, q.y, fmaf(mz, q.z, q.w)));
        if (t < d2) {
            if (t < d1) {
                d2 = d1; i2 = i1;
                if (t < d0) { d1 = d0; i1 = i0; d0 = t; i0 = s; }
                else        { d1 = t;  i1 = s; }
            } else { d2 = t; i2 = s; }
        }
    }
    float e0 = d0 + p2, e1 = d1 + p2, e2 = d2 + p2;
    float r0 = 1.f / (e0 + 1e-8f), r1 = 1.f / (e1 + 1e-8f), r2 = 1.f / (e2 + 1e-8f);
    float rs = 1.f / (r0 + r1 + r2);
    size_t base = ((size_t)b * NN + n) * 3;
    g_idx[base] = i0; g_idx[base + 1] = i1; g_idx[base + 2] = i2;
    g_wt [base] = r0 * rs; g_wt[base + 1] = r1 * rs; g_wt[base + 2] = r2 * rs;
}

// ---------------- weighted gather of 3 rows from P2T -> X[:,128:384] ----------------
__global__ void interp_kernel()
{
    int b  = blockIdx.y;
    int c  = threadIdx.x;                  // channel 0..255
    int n0 = blockIdx.x * 32;
    const float* p2t = g_P2T + (size_t)b * SS * C2K;
#pragma unroll 4
    for (int r = 0; r < 32; r++) {
        size_t m = (size_t)b * NN + n0 + r;
        int   j0 = g_idx[m * 3], j1 = g_idx[m * 3 + 1], j2 = g_idx[m * 3 + 2];
        float w0 = g_wt[m * 3], w1 = g_wt[m * 3 + 1], w2 = g_wt[m * 3 + 2];
        float v = w0 * p2t[(size_t)j0 * C2K + c]
                + w1 * p2t[(size_t)j1 * C2K + c]
                + w2 * p2t[(size_t)j2 * C2K + c];
        g_X[m * INCH + C1K + c] = v;
    }
}

// ---------------- fp32 tiled GEMM: Y[m][n] = sum_k f(A[m][k]) * W[n][k] + bias[n] ----------------
// BM=128, BN=128, BK=16, 256 threads, 8x8 per thread. Optional fused BN+ReLU on A.
template <int K, bool BNRELU>
__global__ __launch_bounds__(256) void gemm_kernel(
    const float* __restrict__ A, const float* __restrict__ W, const float* __restrict__ bias,
    const float* __restrict__ sc, const float* __restrict__ sh,
    float* __restrict__ Y, int ldc)
{
    __shared__ float As[16][132];
    __shared__ float Bs[16][132];
    int tid = threadIdx.x;
    int m0 = blockIdx.x * 128;
    int n0 = blockIdx.y * 128;
    int lr = tid >> 2;            // 0..63 (row within half-tile)
    int lc = (tid & 3) * 4;       // k offset: 0,4,8,12
    int ty = tid >> 4, tx = tid & 15;

    float acc[8][8];
#pragma unroll
    for (int i = 0; i < 8; i++)
#pragma unroll
        for (int j = 0; j < 8; j++) acc[i][j] = 0.f;

    for (int k0 = 0; k0 < K; k0 += 16) {
#pragma unroll
        for (int h = 0; h < 2; h++) {
            int row = lr + h * 64;
            float4 a = *(const float4*)&A[(size_t)(m0 + row) * K + k0 + lc];
            if (BNRELU) {
                float4 s4 = *(const float4*)&sc[k0 + lc];
                float4 t4 = *(const float4*)&sh[k0 + lc];
                a.x = fmaxf(fmaf(a.x, s4.x, t4.x), 0.f);
                a.y = fmaxf(fmaf(a.y, s4.y, t4.y), 0.f);
                a.z = fmaxf(fmaf(a.z, s4.z, t4.z), 0.f);
                a.w = fmaxf(fmaf(a.w, s4.w, t4.w), 0.f);
            }
            As[lc + 0][row] = a.x; As[lc + 1][row] = a.y;
            As[lc + 2][row] = a.z; As[lc + 3][row] = a.w;
            float4 wv = *(const float4*)&W[(size_t)(n0 + row) * K + k0 + lc];
            Bs[lc + 0][row] = wv.x; Bs[lc + 1][row] = wv.y;
            Bs[lc + 2][row] = wv.z; Bs[lc + 3][row] = wv.w;
        }
        __syncthreads();
#pragma unroll
        for (int k = 0; k < 16; k++) {
            float ar[8], br[8];
            *(float4*)&ar[0] = *(const float4*)&As[k][ty * 8];
            *(float4*)&ar[4] = *(const float4*)&As[k][ty * 8 + 4];
            *(float4*)&br[0] = *(const float4*)&Bs[k][tx * 8];
            *(float4*)&br[4] = *(const float4*)&Bs[k][tx * 8 + 4];
#pragma unroll
            for (int i = 0; i < 8; i++)
#pragma unroll
                for (int j = 0; j < 8; j++) acc[i][j] = fmaf(ar[i], br[j], acc[i][j]);
        }
        __syncthreads();
    }

#pragma unroll
    for (int i = 0; i < 8; i++) {
        int m = m0 + ty * 8 + i;
#pragma unroll
        for (int j = 0; j < 8; j += 4) {
            int n = n0 + tx * 8 + j;
            float4 o;
            o.x = acc[i][j]     + bias[n];
            o.y = acc[i][j + 1] + bias[n + 1];
            o.z = acc[i][j + 2] + bias[n + 2];
            o.w = acc[i][j + 3] + bias[n + 3];
            *(float4*)&Y[(size_t)m * ldc + n] = o;
        }
    }
}

// ---------------- per-channel sum / sumsq over all M rows ----------------
__global__ void colstats_kernel(const float* __restrict__ Y, int C,
                                float* __restrict__ sum, float* __restrict__ sq)
{
    int c = threadIdx.x;
    float s = 0.f, q = 0.f;
    for (int m = blockIdx.x; m < MM; m += gridDim.x) {
        float v = Y[(size_t)m * C + c];
        s += v; q = fmaf(v, v, q);
    }
    atomicAdd(&sum[c], s);
    atomicAdd(&sq[c], q);
}

__global__ void finalize_kernel(const float* __restrict__ sum, const float* __restrict__ sq,
                                const float* __restrict__ g, const float* __restrict__ be,
                                float* __restrict__ sc, float* __restrict__ sh)
{
    int c = threadIdx.x;
    float mean = sum[c] * (1.f / MM);
    float var  = sq[c] * (1.f / MM) - mean * mean;
    float s = g[c] * rsqrtf(var + 1e-5f);
    sc[c] = s;
    sh[c] = fmaf(-mean, s, be[c]);
}

// ---------------- BN2 + ReLU + transpose to out[b][c][n] ----------------
__global__ void writeout_kernel(float* __restrict__ out)
{
    __shared__ float tile[32][33];
    int b  = blockIdx.z;
    int n0 = blockIdx.x * 32, c0 = blockIdx.y * 32;
    int tx = threadIdx.x, ty = threadIdx.y;
#pragma unroll
    for (int i = 0; i < 4; i++) {
        int n = n0 + ty + i * 8;
        float v = g_Y2[((size_t)b * NN + n) * H2 + c0 + tx];
        v = fmaxf(fmaf(v, g_sc2[c0 + tx], g_sh2[c0 + tx]), 0.f);
        tile[ty + i * 8][tx] = v;     // tile[n_local][c_local]
    }
    __syncthreads();
#pragma unroll
    for (int i = 0; i < 4; i++) {
        int c = c0 + ty + i * 8;
        out[((size_t)b * H2 + c) * NN + n0 + tx] = tile[tx][ty + i * 8];
    }
}

// ---------------- launch ----------------
extern "C" void kernel_launch(void* const* d_in, const int* in_sizes, int n_in,
                              void* d_out, int out_size)
{
    const float* xyz1    = (const float*)d_in[0];
    const float* xyz2    = (const float*)d_in[1];
    const float* points1 = (const float*)d_in[2];
    const float* points2 = (const float*)d_in[3];
    const float* W1  = (const float*)d_in[4];
    const float* b1  = (const float*)d_in[5];
    const float* g1  = (const float*)d_in[6];
    const float* be1 = (const float*)d_in[7];
    const float* W2  = (const float*)d_in[8];
    const float* b2  = (const float*)d_in[9];
    const float* g2  = (const float*)d_in[10];
    const float* be2 = (const float*)d_in[11];
    float* out = (float*)d_out;

    float *pX, *pY1, *pY2, *pP2T;
    float *psum1, *psq1, *psum2, *psq2, *psc1, *psh1, *psc2, *psh2;
    cudaGetSymbolAddress((void**)&pX,   g_X);
    cudaGetSymbolAddress((void**)&pY1,  g_Y1);
    cudaGetSymbolAddress((void**)&pY2,  g_Y2);
    cudaGetSymbolAddress((void**)&pP2T, g_P2T);
    cudaGetSymbolAddress((void**)&psum1, g_sum1);
    cudaGetSymbolAddress((void**)&psq1,  g_sq1);
    cudaGetSymbolAddress((void**)&psum2, g_sum2);
    cudaGetSymbolAddress((void**)&psq2,  g_sq2);
    cudaGetSymbolAddress((void**)&psc1,  g_sc1);
    cudaGetSymbolAddress((void**)&psh1,  g_sh1);
    cudaGetSymbolAddress((void**)&psc2,  g_sc2);
    cudaGetSymbolAddress((void**)&psh2,  g_sh2);

    zero_stats_kernel<<<1, 256>>>();

    // points1 [B,128,N] -> X[:, 0:128]   (ld 384)
    transpose_kernel<<<dim3(NN / 32, C1K / 32, BB), dim3(32, 8)>>>(points1, pX, C1K, NN, INCH);
    // points2 [B,256,S] -> P2T [B,S,256]
    transpose_kernel<<<dim3(SS / 32, C2K / 32, BB), dim3(32, 8)>>>(points2, pP2T, C2K, SS, C2K);

    knn_kernel<<<dim3(NN / 256, BB), 256>>>(xyz1, xyz2);
    interp_kernel<<<dim3(NN / 32, BB), 256>>>();

    // layer 1: [M,384] @ [384,256]
    gemm_kernel<INCH, false><<<dim3(MM / 128, H1 / 128), 256>>>(pX, W1, b1, nullptr, nullptr, pY1, H1);
    colstats_kernel<<<256, H1>>>(pY1, H1, psum1, psq1);
    finalize_kernel<<<1, H1>>>(psum1, psq1, g1, be1, psc1, psh1);

    // layer 2: BN1+ReLU fused into A-load, [M,256] @ [256,128]
    gemm_kernel<H1, true><<<dim3(MM / 128, H2 / 128), 256>>>(pY1, W2, b2, psc1, psh1, pY2, H2);
    colstats_kernel<<<256, H2>>>(pY2, H2, psum2, psq2);
    finalize_kernel<<<1, H2>>>(psum2, psq2, g2, be2, psc2, psh2);

    // BN2 + ReLU + transpose to [B,128,N]
    writeout_kernel<<<dim3(NN / 32, H2 / 32, BB), dim3(32, 8)>>>(out);
}